// round 2
// baseline (speedup 1.0000x reference)
#include <cuda_runtime.h>
#include <math.h>
#include <stdint.h>

#define K_COMP 8192
#define N_SAMP 8192
#define B_X    2048
#define D_W    13
#define NCHUNK 8

#define LOG_2PI 1.8378770664093453f
#define L2E     1.4426950408889634f

// ---------------- scratch (no allocations allowed) ----------------
__device__ float g_empT[D_W][K_COMP];   // emp transposed [k][n]
__device__ float g_wT[D_W][N_SAMP];     // w transposed  [k][b]
__device__ float g_std[K_COMP];
__device__ float g_c[K_COMP];
__device__ float g_u[K_COMP];           // L2E*(c_k - 0.5*inv_var*en_k)
__device__ float g_g[K_COMP];           // L2E*inv_var
__device__ float g_wn[N_SAMP];          // ||w_b||^2
__device__ float g_mln[N_SAMP];         // shift M_b (natural log domain)
__device__ float g_dsum[N_SAMP];        // sum_k (y_pred - y)^2
__device__ float g_Spart[NCHUNK][N_SAMP];

__device__ __forceinline__ float tanh_fast(float x) {
    float r;
    asm("tanh.approx.f32 %0, %1;" : "=f"(r) : "f"(x));
    return r;
}
__device__ __forceinline__ float exp2_fast(float x) {
    float r;
    asm("ex2.approx.f32 %0, %1;" : "=f"(r) : "f"(x));
    return r;
}

// ---------------- kernel 1: per-component precompute ----------------
__global__ void prep_k(const float* __restrict__ emp, const float* __restrict__ rhos) {
    int k = blockIdx.x * blockDim.x + threadIdx.x;
    if (k >= K_COMP) return;
    float rho = rhos[k];
    float sd = (rho > 20.f) ? rho : log1pf(__expf(rho));   // softplus
    float var = sd * sd;
    float inv = 1.f / var;
    float en = 0.f;
#pragma unroll
    for (int d = 0; d < D_W; d++) {
        float v = __ldg(&emp[k * D_W + d]);
        g_empT[d][k] = v;
        en = fmaf(v, v, en);
    }
    float c = -0.5f * ((float)D_W * LOG_2PI + (float)D_W * logf(var));
    g_std[k] = sd;
    g_c[k]   = c;
    g_u[k]   = L2E * (c - 0.5f * inv * en);
    g_g[k]   = L2E * inv;
}

// ---------------- kernel 2: per-sample w, norms, shift ----------------
__global__ void prep_s(const float* __restrict__ emp, const float* __restrict__ eps,
                       const int* __restrict__ idxs) {
    int s = blockIdx.x * blockDim.x + threadIdx.x;
    if (s >= N_SAMP) return;
    int idx = idxs[s];
    float sd = g_std[idx];
    float wn = 0.f, epsn = 0.f;
#pragma unroll
    for (int d = 0; d < D_W; d++) {
        float e = __ldg(&eps[s * D_W + d]);
        float w = fmaf(e, sd, __ldg(&emp[idx * D_W + d]));
        g_wT[d][s] = w;
        wn = fmaf(w, w, wn);
        epsn = fmaf(e, e, epsn);
    }
    g_wn[s]  = wn;
    g_mln[s] = g_c[idx] - 0.5f * epsn;   // comp_lp at own component (valid shift)
}

// ---------------- kernel 3: regression data term ----------------
// one warp per sample; x,y staged in smem
__global__ __launch_bounds__(1024) void reg_kernel(const float* __restrict__ x,
                                                   const float* __restrict__ y) {
    __shared__ float sx[B_X];
    __shared__ float sy[B_X];
    for (int i = threadIdx.x; i < B_X; i += blockDim.x) { sx[i] = x[i]; sy[i] = y[i]; }
    __syncthreads();

    int warp = threadIdx.x >> 5, lane = threadIdx.x & 31;
    int s = blockIdx.x * (blockDim.x >> 5) + warp;

    float p[D_W];
#pragma unroll
    for (int d = 0; d < D_W; d++) p[d] = g_wT[d][s];
    float w10 = p[0], w11 = p[1], b10 = p[2], b11 = p[3];
    float w200 = p[4], w201 = p[5], w210 = p[6], w211 = p[7];
    float b20 = p[8], b21 = p[9], w30 = p[10], w31 = p[11], b3 = p[12];

    float acc = 0.f;
#pragma unroll 4
    for (int t = 0; t < B_X / 32; t++) {
        int pix = t * 32 + lane;
        float xv = sx[pix], yv = sy[pix];
        float h0 = tanh_fast(fmaf(w10, xv, b10));
        float h1 = tanh_fast(fmaf(w11, xv, b11));
        float z0 = tanh_fast(fmaf(w200, h0, fmaf(w201, h1, b20)));
        float z1 = tanh_fast(fmaf(w210, h0, fmaf(w211, h1, b21)));
        float yp = fmaf(w30, z0, fmaf(w31, z1, b3));
        float d = yp - yv;
        acc = fmaf(d, d, acc);
    }
#pragma unroll
    for (int o = 16; o; o >>= 1) acc += __shfl_xor_sync(0xffffffffu, acc, o);
    if (lane == 0) g_dsum[s] = acc;
}

// ---------------- kernel 4: GEMM + shifted exp-sum ----------------
// block: 256 threads (16x16), tile 128(M) x 128(N), K=13
#define MT 128
#define NT 128
__global__ __launch_bounds__(256) void lse_kernel() {
    __shared__ float sw[D_W][MT];
    __shared__ float se[D_W][NT];
    __shared__ float su[NT];
    __shared__ float sg[NT];

    int tid = threadIdx.x;
    int tx = tid & 15;        // N direction
    int ty = tid >> 4;        // M direction
    int m0 = blockIdx.x * MT;
    int n0base = blockIdx.y * (K_COMP / NCHUNK);

    // load w tile once (reused across all N tiles)
    for (int i = tid; i < D_W * MT; i += 256) {
        int d = i / MT, c = i % MT;
        sw[d][c] = g_wT[d][m0 + c];
    }
    float wnh[8], m2[8], S[8];
#pragma unroll
    for (int r = 0; r < 8; r++) {
        int row = m0 + ty * 8 + r;
        wnh[r] = -0.5f * g_wn[row];
        m2[r]  = L2E * g_mln[row];
        S[r]   = 0.f;
    }

    const int NTILES = (K_COMP / NCHUNK) / NT;   // 8
    for (int nt = 0; nt < NTILES; nt++) {
        int n0 = n0base + nt * NT;
        __syncthreads();
        for (int i = tid; i < D_W * NT; i += 256) {
            int d = i / NT, c = i % NT;
            se[d][c] = g_empT[d][n0 + c];
        }
        if (tid < NT) { su[tid] = g_u[n0 + tid]; sg[tid] = g_g[n0 + tid]; }
        __syncthreads();

        float acc[8][8];
#pragma unroll
        for (int r = 0; r < 8; r++)
#pragma unroll
            for (int c = 0; c < 8; c++) acc[r][c] = wnh[r];   // A = dot - 0.5||w||^2

#pragma unroll
        for (int k = 0; k < D_W; k++) {
            float4 wa = *(const float4*)&sw[k][ty * 8];
            float4 wb = *(const float4*)&sw[k][ty * 8 + 4];
            float4 ea = *(const float4*)&se[k][tx * 8];
            float4 eb = *(const float4*)&se[k][tx * 8 + 4];
            float wr[8] = {wa.x, wa.y, wa.z, wa.w, wb.x, wb.y, wb.z, wb.w};
            float ec[8] = {ea.x, ea.y, ea.z, ea.w, eb.x, eb.y, eb.z, eb.w};
#pragma unroll
            for (int r = 0; r < 8; r++)
#pragma unroll
                for (int c = 0; c < 8; c++)
                    acc[r][c] = fmaf(wr[r], ec[c], acc[r][c]);
        }

        // epilogue: arg2 = g_k * A + u_k - m2_b ; S += 2^arg2
#pragma unroll
        for (int c = 0; c < 8; c++) {
            float gg = sg[tx * 8 + c];
            float uu = su[tx * 8 + c];
#pragma unroll
            for (int r = 0; r < 8; r++) {
                float t = fmaf(gg, acc[r][c], uu) - m2[r];
                S[r] += exp2_fast(t);
            }
        }
    }

    // reduce across the 16 tx lanes (they live in one half-warp)
#pragma unroll
    for (int r = 0; r < 8; r++) {
        float v = S[r];
#pragma unroll
        for (int o = 8; o; o >>= 1) v += __shfl_xor_sync(0xffffffffu, v, o);
        if (tx == 0) g_Spart[blockIdx.y][m0 + ty * 8 + r] = v;
    }
}

// ---------------- kernel 5: final deterministic reduction ----------------
__global__ __launch_bounds__(1024) void final_kernel(float* __restrict__ out) {
    __shared__ double sh[3][32];
    int tid = threadIdx.x;
    double qs = 0.0, wns = 0.0, ds = 0.0;
    for (int s = tid; s < N_SAMP; s += 1024) {
        float S = 0.f;
#pragma unroll
        for (int c = 0; c < NCHUNK; c++) S += g_Spart[c][s];
        qs  += (double)(g_mln[s] + logf(S));
        wns += (double)g_wn[s];
        ds  += (double)g_dsum[s];
    }
    int lane = tid & 31, warp = tid >> 5;
#pragma unroll
    for (int o = 16; o; o >>= 1) {
        qs  += __shfl_xor_sync(0xffffffffu, qs, o);
        wns += __shfl_xor_sync(0xffffffffu, wns, o);
        ds  += __shfl_xor_sync(0xffffffffu, ds, o);
    }
    if (lane == 0) { sh[0][warp] = qs; sh[1][warp] = wns; sh[2][warp] = ds; }
    __syncthreads();
    if (warp == 0) {
        qs = sh[0][lane]; wns = sh[1][lane]; ds = sh[2][lane];
#pragma unroll
        for (int o = 16; o; o >>= 1) {
            qs  += __shfl_xor_sync(0xffffffffu, qs, o);
            wns += __shfl_xor_sync(0xffffffffu, wns, o);
            ds  += __shfl_xor_sync(0xffffffffu, ds, o);
        }
        if (lane == 0) {
            const double LOG_2PI_D = 1.837877066409345483560659472811;
            double mean_q  = qs / (double)N_SAMP - log((double)K_COMP);
            double mean_wn = wns / (double)N_SAMP;
            double mean_d  = ds / (double)N_SAMP;
            double data_lp = -0.5 * 5.0 * mean_d
                           + (double)B_X * 0.5 * (log(5.0) - LOG_2PI_D);
            double prior   = -0.5 * mean_wn - 0.5 * (double)D_W * LOG_2PI_D;
            double kl      = mean_q - prior;
            out[0] = (float)(data_lp - kl);
        }
    }
}

// ---------------- launch ----------------
extern "C" void kernel_launch(void* const* d_in, const int* in_sizes, int n_in,
                              void* d_out, int out_size) {
    const float* emp  = (const float*)d_in[0];
    const float* rhos = (const float*)d_in[1];
    const float* x    = (const float*)d_in[2];
    const float* y    = (const float*)d_in[3];
    const float* eps  = (const float*)d_in[4];
    const int*   idxs = (const int*)d_in[5];
    float* out = (float*)d_out;

    prep_k<<<(K_COMP + 255) / 256, 256>>>(emp, rhos);
    prep_s<<<(N_SAMP + 255) / 256, 256>>>(emp, eps, idxs);
    reg_kernel<<<N_SAMP / 32, 1024>>>(x, y);
    lse_kernel<<<dim3(N_SAMP / MT, NCHUNK), 256>>>();
    final_kernel<<<1, 1024>>>(out);
}